// round 16
// baseline (speedup 1.0000x reference)
#include <cuda_runtime.h>
#include <cuda_bf16.h>
#include <cstdint>

// Problem constants (fixed by the dataset)
#define NN   50000
#define EE   800000
#define INF  256
#define OUTF 32
#define NH   8
#define CC   256   // NH * OUTF

#define NBLK ((NN + 255) / 256)   // 196 scan blocks

// ---------------- scratch (device globals; no allocs allowed) ----------------
__device__ __align__(16) float g_h[NN * CC];        // 51.2 MB  [N, H*F]
__device__ __align__(16) float g_ssrc[NN * NH];     // per-node src logits [N,8]
__device__ __align__(16) float g_sdst[NN * NH];     // per-node dst logits [N,8]
__device__ int g_deg[NN];
__device__ int g_rowptr[NN + 1];
__device__ int g_cursor[NN];
__device__ int g_csrc[EE];
__device__ int g_bsum[NBLK];
__device__ int g_boff[NBLK];
// B operand pre-packed in mma.sync m16n8k16 B-fragment layout:
// [tier(hi/lo)][kstep 0..15][ntile 0..31][lane 0..31] -> uint2 (b0,b1)
__device__ __align__(16) uint2 g_Bf[2 * 16 * 32 * 32];

// ---------------- helpers ----------------
__device__ __forceinline__ uint32_t smem_u32(const void* p) {
    uint32_t a;
    asm("{ .reg .u64 t; cvta.to.shared.u64 t, %1; cvt.u32.u64 %0, t; }" : "=r"(a) : "l"(p));
    return a;
}
__device__ __forceinline__ float lrelu_exp(float a, float b) {
    float v = a + b;
    v = v > 0.f ? v : 0.2f * v;
    return __expf(v);
}
__device__ __forceinline__ uint32_t pack_bf2(__nv_bfloat16 a, __nv_bfloat16 b) {
    __nv_bfloat162 t = __nv_bfloat162(a, b);
    return *(uint32_t*)&t;
}
__device__ __forceinline__ void mma16816(float* d, const uint32_t* a, const uint2 b) {
    asm volatile(
        "mma.sync.aligned.m16n8k16.row.col.f32.bf16.bf16.f32 "
        "{%0,%1,%2,%3}, {%4,%5,%6,%7}, {%8,%9}, {%0,%1,%2,%3};"
        : "+f"(d[0]), "+f"(d[1]), "+f"(d[2]), "+f"(d[3])
        : "r"(a[0]), "r"(a[1]), "r"(a[2]), "r"(a[3]), "r"(b.x), "r"(b.y));
}
__device__ __forceinline__ void ldmat4(uint32_t* r, uint32_t addr) {
    asm volatile("ldmatrix.sync.aligned.m8n8.x4.shared.b16 {%0,%1,%2,%3}, [%4];"
                 : "=r"(r[0]), "=r"(r[1]), "=r"(r[2]), "=r"(r[3]) : "r"(addr));
}

// ---------------- 0) zero degree histogram ----------------
__global__ void zero_deg_kernel() {
    int i = blockIdx.x * blockDim.x + threadIdx.x;
    if (i < NN) g_deg[i] = 0;
    if (i == 0) g_rowptr[NN] = EE;
}

// ---------------- 0b) prep B fragments ----------------
// Logical B[n][k] = W[n>>5][k][n&31]  (n = output column, k = input feature).
// mma m16n8k16 B frag (col-major B): thread 'lane' holds
//   b0 = {B(k0, n), B(k0+1, n)},  b1 = {B(k0+8, n), B(k0+9, n)}
// with n = ntile*8 + lane/4, k0 = kstep*16 + (lane&3)*2.
__global__ __launch_bounds__(256) void prep_bfrag_kernel(const float* __restrict__ W) {
    int idx  = blockIdx.x * 256 + threadIdx.x;   // 32768 total
    int lane = idx & 31;
    int nt   = (idx >> 5) & 31;
    int ks   = (idx >> 10) & 15;
    int tier = idx >> 14;
    int n  = nt * 8 + (lane >> 2);
    int k0 = ks * 16 + (lane & 3) * 2;
    __nv_bfloat16 v[4];
#pragma unroll
    for (int q = 0; q < 4; q++) {
        int k = k0 + (q >> 1) * 8 + (q & 1);
        float w = W[(n >> 5) * (INF * OUTF) + k * OUTF + (n & 31)];
        __nv_bfloat16 hi = __float2bfloat16(w);
        v[q] = (tier == 0) ? hi : __float2bfloat16(w - __bfloat162float(hi));
    }
    g_Bf[idx] = make_uint2(pack_bf2(v[0], v[1]), pack_bf2(v[2], v[3]));
}

// ---------------- 1) mma.sync split-bf16 GEMM + fused logits ----------------
// 512 threads, CTA tile 128x256 (full N). Warp grid 4m x 4n; warp tile 32x64.
// A converted fp32 -> hi/lo bf16 into padded smem [128][72] per tier
// (144B row stride -> conflict-free ldmatrix). K chunked x64 (4 chunks).
// D = Ahi*Bhi + Ahi*Blo + Alo*Bhi, fp32 accum (error ~2^-16).
__global__ __launch_bounds__(512) void gemm_mma_kernel(const float* __restrict__ x,
                                                       const float* __restrict__ a_src,
                                                       const float* __restrict__ a_dst) {
    __shared__ uint16_t sA[2][128 * 72];   // 36 KB: [tier][row*72 + k]
    __shared__ float sAs[CC], sAd[CC];

    const int tid  = threadIdx.x;
    const int warp = tid >> 5;
    const int lane = tid & 31;
    const int mw   = warp >> 2;      // 0..3
    const int nw   = warp & 3;       // 0..3
    const int bm   = blockIdx.x * 128;
    const int g    = lane >> 2;      // row group within m8
    const int tq   = lane & 3;

    if (tid < CC) { sAs[tid] = a_src[tid]; sAd[tid] = a_dst[tid]; }

    float acc[2][8][4];
#pragma unroll
    for (int mt = 0; mt < 2; mt++)
#pragma unroll
        for (int j = 0; j < 8; j++)
#pragma unroll
            for (int q = 0; q < 4; q++) acc[mt][j][q] = 0.f;

    const uint32_t sA0 = smem_u32(&sA[0][0]);
    const uint32_t sA1 = smem_u32(&sA[1][0]);

    for (int c = 0; c < 4; c++) {
        __syncthreads();   // protect smem reuse from previous chunk's ldmatrix
        // ---- load + convert A chunk: 128 rows x 64 k ----
#pragma unroll
        for (int i = 0; i < 4; i++) {
            int j  = tid + i * 512;        // 0..2047
            int r  = j >> 4;
            int k4 = (j & 15) << 2;
            int gr = bm + r;
            float4 v = make_float4(0.f, 0.f, 0.f, 0.f);
            if (gr < NN) v = *(const float4*)&x[gr * INF + c * 64 + k4];
            __nv_bfloat16 h0 = __float2bfloat16(v.x), h1 = __float2bfloat16(v.y);
            __nv_bfloat16 h2 = __float2bfloat16(v.z), h3 = __float2bfloat16(v.w);
            __nv_bfloat16 l0 = __float2bfloat16(v.x - __bfloat162float(h0));
            __nv_bfloat16 l1 = __float2bfloat16(v.y - __bfloat162float(h1));
            __nv_bfloat16 l2 = __float2bfloat16(v.z - __bfloat162float(h2));
            __nv_bfloat16 l3 = __float2bfloat16(v.w - __bfloat162float(h3));
            int o = r * 72 + k4;
            *(uint2*)&sA[0][o] = make_uint2(pack_bf2(h0, h1), pack_bf2(h2, h3));
            *(uint2*)&sA[1][o] = make_uint2(pack_bf2(l0, l1), pack_bf2(l2, l3));
        }
        __syncthreads();

        // ---- 4 k-steps of K=16 within this chunk ----
#pragma unroll
        for (int ks = 0; ks < 4; ks++) {
            const int gk = c * 4 + ks;
            // ldmatrix addressing: lanes 0-15 rows, lanes 16-31 select k-half
            uint32_t arow  = lane & 15;
            uint32_t ahalf = lane >> 4;
            uint32_t ahi0[4], ahi1[4], alo0[4], alo1[4];
            uint32_t off0 = ((mw * 32 + 0  + arow) * 72 + ks * 16 + ahalf * 8) * 2;
            uint32_t off1 = ((mw * 32 + 16 + arow) * 72 + ks * 16 + ahalf * 8) * 2;
            ldmat4(ahi0, sA0 + off0);
            ldmat4(ahi1, sA0 + off1);
            ldmat4(alo0, sA1 + off0);
            ldmat4(alo1, sA1 + off1);

            const uint2* bfh = &g_Bf[((0 * 16 + gk) * 32 + nw * 8) * 32 + lane];
            const uint2* bfl = &g_Bf[((1 * 16 + gk) * 32 + nw * 8) * 32 + lane];
#pragma unroll
            for (int j = 0; j < 8; j++) {
                uint2 bh = bfh[j * 32];
                uint2 bl = bfl[j * 32];
                mma16816(acc[0][j], ahi0, bh);
                mma16816(acc[1][j], ahi1, bh);
                mma16816(acc[0][j], ahi0, bl);
                mma16816(acc[1][j], ahi1, bl);
                mma16816(acc[0][j], alo0, bh);
                mma16816(acc[1][j], alo1, bh);
            }
        }
    }
    __syncthreads();

    // ---- epilogue: store h + fused logits ----
    // Thread's elements: rows r0 = bm + mw*32 + mt*16 + g, r1 = r0 + 8;
    // cols = nw*64 + j*8 + 2*tq (+1). Heads covered by warp: nw*2 + (j>=4).
    float ps[2][2][2] = {}, pd[2][2][2] = {};   // [mt][rowhalf][head]
#pragma unroll
    for (int mt = 0; mt < 2; mt++) {
        int r0 = bm + mw * 32 + mt * 16 + g;
        int r1 = r0 + 8;
#pragma unroll
        for (int j = 0; j < 8; j++) {
            int col = nw * 64 + j * 8 + tq * 2;
            int hh  = j >> 2;
            float a0 = sAs[col], a1 = sAs[col + 1];
            float d0 = sAd[col], d1 = sAd[col + 1];
            ps[mt][0][hh] += acc[mt][j][0] * a0 + acc[mt][j][1] * a1;
            pd[mt][0][hh] += acc[mt][j][0] * d0 + acc[mt][j][1] * d1;
            ps[mt][1][hh] += acc[mt][j][2] * a0 + acc[mt][j][3] * a1;
            pd[mt][1][hh] += acc[mt][j][2] * d0 + acc[mt][j][3] * d1;
            if (r0 < NN)
                *(float2*)&g_h[r0 * CC + col] = make_float2(acc[mt][j][0], acc[mt][j][1]);
            if (r1 < NN)
                *(float2*)&g_h[r1 * CC + col] = make_float2(acc[mt][j][2], acc[mt][j][3]);
        }
    }
    // quad reduction (lanes 4g..4g+3 share a row)
#pragma unroll
    for (int mt = 0; mt < 2; mt++)
#pragma unroll
        for (int hf = 0; hf < 2; hf++)
#pragma unroll
            for (int hh = 0; hh < 2; hh++) {
                ps[mt][hf][hh] += __shfl_xor_sync(0xffffffffu, ps[mt][hf][hh], 1, 4);
                ps[mt][hf][hh] += __shfl_xor_sync(0xffffffffu, ps[mt][hf][hh], 2, 4);
                pd[mt][hf][hh] += __shfl_xor_sync(0xffffffffu, pd[mt][hf][hh], 1, 4);
                pd[mt][hf][hh] += __shfl_xor_sync(0xffffffffu, pd[mt][hf][hh], 2, 4);
            }
    if (tq == 0) {
#pragma unroll
        for (int mt = 0; mt < 2; mt++) {
            int r0 = bm + mw * 32 + mt * 16 + g;
            int r1 = r0 + 8;
#pragma unroll
            for (int hh = 0; hh < 2; hh++) {
                int hcol = nw * 2 + hh;
                if (r0 < NN) {
                    g_ssrc[r0 * NH + hcol] = ps[mt][0][hh];
                    g_sdst[r0 * NH + hcol] = pd[mt][0][hh];
                }
                if (r1 < NN) {
                    g_ssrc[r1 * NH + hcol] = ps[mt][1][hh];
                    g_sdst[r1 * NH + hcol] = pd[mt][1][hh];
                }
            }
        }
    }
}

// ---------------- 2) CSR build: histogram -> 3-stage scan -> scatter ----------------
__global__ void hist_kernel(const int* __restrict__ ei) {
    int e = blockIdx.x * blockDim.x + threadIdx.x;
    if (e >= EE) return;
    atomicAdd(&g_deg[ei[EE + e]], 1);
}

__global__ __launch_bounds__(256) void scan_bsum_kernel() {
    __shared__ int ws[8];
    int i = blockIdx.x * 256 + threadIdx.x;
    int v = (i < NN) ? g_deg[i] : 0;
    int lane = threadIdx.x & 31, wid = threadIdx.x >> 5;
#pragma unroll
    for (int off = 16; off; off >>= 1) v += __shfl_xor_sync(0xffffffffu, v, off);
    if (lane == 0) ws[wid] = v;
    __syncthreads();
    if (threadIdx.x == 0) {
        int s = 0;
#pragma unroll
        for (int w = 0; w < 8; w++) s += ws[w];
        g_bsum[blockIdx.x] = s;
    }
}

__global__ __launch_bounds__(256) void scan_boff_kernel() {
    __shared__ int ws[8];
    int t = threadIdx.x;
    int s = (t < NBLK) ? g_bsum[t] : 0;
    int lane = t & 31, wid = t >> 5;
    int v = s;
#pragma unroll
    for (int off = 1; off < 32; off <<= 1) {
        int u = __shfl_up_sync(0xffffffffu, v, off);
        if (lane >= off) v += u;
    }
    if (lane == 31) ws[wid] = v;
    __syncthreads();
    if (wid == 0 && lane < 8) {
        int w = ws[lane];
#pragma unroll
        for (int off = 1; off < 8; off <<= 1) {
            int u = __shfl_up_sync(0x000000ffu, w, off);
            if (lane >= off) w += u;
        }
        ws[lane] = w;
    }
    __syncthreads();
    int excl = v - s + (wid ? ws[wid - 1] : 0);
    if (t < NBLK) g_boff[t] = excl;
}

__global__ __launch_bounds__(256) void scan_write_kernel() {
    __shared__ int ws[8];
    int i = blockIdx.x * 256 + threadIdx.x;
    int s = (i < NN) ? g_deg[i] : 0;
    int lane = threadIdx.x & 31, wid = threadIdx.x >> 5;
    int v = s;
#pragma unroll
    for (int off = 1; off < 32; off <<= 1) {
        int u = __shfl_up_sync(0xffffffffu, v, off);
        if (lane >= off) v += u;
    }
    if (lane == 31) ws[wid] = v;
    __syncthreads();
    if (wid == 0 && lane < 8) {
        int w = ws[lane];
#pragma unroll
        for (int off = 1; off < 8; off <<= 1) {
            int u = __shfl_up_sync(0x000000ffu, w, off);
            if (lane >= off) w += u;
        }
        ws[lane] = w;
    }
    __syncthreads();
    int excl = v - s + (wid ? ws[wid - 1] : 0) + g_boff[blockIdx.x];
    if (i < NN) {
        g_rowptr[i] = excl;
        g_cursor[i] = excl;
    }
}

__global__ void scatter_kernel(const int* __restrict__ ei) {
    int e = blockIdx.x * blockDim.x + threadIdx.x;
    if (e >= EE) return;
    int src = ei[e];
    int dst = ei[EE + e];
    int p = atomicAdd(&g_cursor[dst], 1);
    g_csrc[p] = src;
}

// ---------------- 3) per-dst softmax + aggregation (no output atomics) ----------
__global__ __launch_bounds__(256) void aggregate_csr_kernel(float* __restrict__ out) {
    int warp = (blockIdx.x * blockDim.x + threadIdx.x) >> 5;
    int lane = threadIdx.x & 31;
    if (warp >= NN) return;
    const int dst   = warp;
    const int start = g_rowptr[dst];
    const int end   = g_rowptr[dst + 1];

    const float4* s4 = (const float4*)g_ssrc;
    float4 d0 = ((const float4*)g_sdst)[dst * 2];
    float4 d1 = ((const float4*)g_sdst)[dst * 2 + 1];

    // pass 1: denominators
    float tot[8] = {0.f, 0.f, 0.f, 0.f, 0.f, 0.f, 0.f, 0.f};
    for (int i = start + lane; i < end; i += 32) {
        int src = g_csrc[i];
        float4 a0 = s4[src * 2], a1 = s4[src * 2 + 1];
        tot[0] += lrelu_exp(a0.x, d0.x);
        tot[1] += lrelu_exp(a0.y, d0.y);
        tot[2] += lrelu_exp(a0.z, d0.z);
        tot[3] += lrelu_exp(a0.w, d0.w);
        tot[4] += lrelu_exp(a1.x, d1.x);
        tot[5] += lrelu_exp(a1.y, d1.y);
        tot[6] += lrelu_exp(a1.z, d1.z);
        tot[7] += lrelu_exp(a1.w, d1.w);
    }
#pragma unroll
    for (int h = 0; h < 8; h++)
#pragma unroll
        for (int off = 16; off; off >>= 1)
            tot[h] += __shfl_xor_sync(0xffffffffu, tot[h], off);

    float inv = 0.f, sdl = 0.f;
    if (lane < NH) {
        sdl = g_sdst[dst * NH + lane];
        float th = tot[0];
#pragma unroll
        for (int h = 1; h < 8; h++) if (lane == h) th = tot[h];
        inv = 1.0f / th;
    }

    // pass 2: weighted accumulation
    float4 acc0 = make_float4(0.f, 0.f, 0.f, 0.f);
    float4 acc1 = make_float4(0.f, 0.f, 0.f, 0.f);
    const float4* h4 = (const float4*)g_h;
    int i = start;
    int src = (i < end) ? g_csrc[i] : 0;
    for (; i < end; i++) {
        int nsrc = (i + 1 < end) ? g_csrc[i + 1] : 0;
        float w = 0.f;
        if (lane < NH) {
            float a = g_ssrc[src * NH + lane];
            float v = a + sdl;
            v = v > 0.f ? v : 0.2f * v;
            w = __expf(v) * inv;
        }
        float wv = __shfl_sync(0xffffffffu, w, lane >> 2);
        float4 v0 = h4[src * (CC / 4) + lane * 2];
        float4 v1 = h4[src * (CC / 4) + lane * 2 + 1];
        acc0.x += wv * v0.x; acc0.y += wv * v0.y;
        acc0.z += wv * v0.z; acc0.w += wv * v0.w;
        acc1.x += wv * v1.x; acc1.y += wv * v1.y;
        acc1.z += wv * v1.z; acc1.w += wv * v1.w;
        src = nsrc;
    }

    float4* o4 = (float4*)(out + dst * CC);
    o4[lane * 2]     = acc0;
    o4[lane * 2 + 1] = acc1;
}

// ---------------- launch ----------------
extern "C" void kernel_launch(void* const* d_in, const int* in_sizes, int n_in,
                              void* d_out, int out_size) {
    const float* x     = (const float*)d_in[0];
    const int*   ei    = (const int*)d_in[1];
    const float* W     = (const float*)d_in[2];
    const float* a_src = (const float*)d_in[3];
    const float* a_dst = (const float*)d_in[4];
    float* out = (float*)d_out;

    zero_deg_kernel<<<(NN + 255) / 256, 256>>>();
    prep_bfrag_kernel<<<128, 256>>>(W);

    gemm_mma_kernel<<<(NN + 127) / 128, 512>>>(x, a_src, a_dst);

    hist_kernel<<<(EE + 255) / 256, 256>>>(ei);
    scan_bsum_kernel<<<NBLK, 256>>>();
    scan_boff_kernel<<<1, 256>>>();
    scan_write_kernel<<<NBLK, 256>>>();
    scatter_kernel<<<(EE + 255) / 256, 256>>>(ei);

    aggregate_csr_kernel<<<NN / 8, 256>>>(out);
}

// round 17
// speedup vs baseline: 1.0028x; 1.0028x over previous
#include <cuda_runtime.h>
#include <cuda_bf16.h>
#include <cstdint>

// Problem constants (fixed by the dataset)
#define NN   50000
#define EE   800000
#define INF  256
#define OUTF 32
#define NH   8
#define CC   256   // NH * OUTF

#define NBLK ((NN + 255) / 256)   // 196 scan blocks

// ---------------- scratch (device globals; no allocs allowed) ----------------
__device__ __align__(16) float g_h[NN * CC];        // 51.2 MB  [N, H*F]
__device__ __align__(16) float g_ssrc[NN * NH];     // per-node src logits [N,8]
__device__ __align__(16) float g_sdst[NN * NH];     // per-node dst logits [N,8]
__device__ int g_deg[NN];
__device__ int g_rowptr[NN + 1];
__device__ int g_cursor[NN];
__device__ int g_csrc[EE];
__device__ int g_bsum[NBLK];
__device__ int g_boff[NBLK];
// B operand pre-packed in mma.sync m16n8k16 B-fragment layout:
// [tier(hi/lo)][kstep 0..15][ntile 0..31][lane 0..31] -> uint2 (b0,b1)
__device__ __align__(16) uint2 g_Bf[2 * 16 * 32 * 32];

// ---------------- helpers ----------------
__device__ __forceinline__ uint32_t smem_u32(const void* p) {
    uint32_t a;
    asm("{ .reg .u64 t; cvta.to.shared.u64 t, %1; cvt.u32.u64 %0, t; }" : "=r"(a) : "l"(p));
    return a;
}
__device__ __forceinline__ uint32_t pack_bf2(__nv_bfloat16 a, __nv_bfloat16 b) {
    __nv_bfloat162 t = __nv_bfloat162(a, b);
    return *(uint32_t*)&t;
}
__device__ __forceinline__ void mma16816(float* d, const uint32_t* a, const uint2 b) {
    asm volatile(
        "mma.sync.aligned.m16n8k16.row.col.f32.bf16.bf16.f32 "
        "{%0,%1,%2,%3}, {%4,%5,%6,%7}, {%8,%9}, {%0,%1,%2,%3};"
        : "+f"(d[0]), "+f"(d[1]), "+f"(d[2]), "+f"(d[3])
        : "r"(a[0]), "r"(a[1]), "r"(a[2]), "r"(a[3]), "r"(b.x), "r"(b.y));
}
__device__ __forceinline__ void ldmat4(uint32_t* r, uint32_t addr) {
    asm volatile("ldmatrix.sync.aligned.m8n8.x4.shared.b16 {%0,%1,%2,%3}, [%4];"
                 : "=r"(r[0]), "=r"(r[1]), "=r"(r[2]), "=r"(r[3]) : "r"(addr));
}

// ---------------- 0) init: zero degree histogram + prep B fragments ----------------
// Blocks [0, NBLK): zero g_deg.  Blocks [NBLK, NBLK+128): pack B fragments.
// Logical B[n][k] = W[n>>5][k][n&31].  mma m16n8k16 B frag (col-major B):
//   lane holds b0 = {B(k0,n), B(k0+1,n)}, b1 = {B(k0+8,n), B(k0+9,n)}
//   with n = ntile*8 + lane/4, k0 = kstep*16 + (lane&3)*2.
__global__ __launch_bounds__(256) void init_kernel(const float* __restrict__ W) {
    if (blockIdx.x < NBLK) {
        int i = blockIdx.x * 256 + threadIdx.x;
        if (i < NN) g_deg[i] = 0;
        if (i == 0) g_rowptr[NN] = EE;
        return;
    }
    int idx  = (blockIdx.x - NBLK) * 256 + threadIdx.x;   // 32768 total
    int lane = idx & 31;
    int nt   = (idx >> 5) & 31;
    int ks   = (idx >> 10) & 15;
    int tier = idx >> 14;
    int n  = nt * 8 + (lane >> 2);
    int k0 = ks * 16 + (lane & 3) * 2;
    __nv_bfloat16 v[4];
#pragma unroll
    for (int q = 0; q < 4; q++) {
        int k = k0 + (q >> 1) * 8 + (q & 1);
        float w = W[(n >> 5) * (INF * OUTF) + k * OUTF + (n & 31)];
        __nv_bfloat16 hi = __float2bfloat16(w);
        v[q] = (tier == 0) ? hi : __float2bfloat16(w - __bfloat162float(hi));
    }
    g_Bf[idx] = make_uint2(pack_bf2(v[0], v[1]), pack_bf2(v[2], v[3]));
}

// ---------------- 1) mma.sync split-bf16 GEMM + fused logits + hist tail ----------
// 512 threads, CTA tile 128x256 (full N). Warp grid 4m x 4n; warp tile 32x64.
// A converted fp32 -> hi/lo bf16 into padded smem [128][72] per tier
// (144B row stride -> conflict-free ldmatrix). K chunked x64 (4 chunks),
// next chunk's x prefetched into registers under the MMA loop.
// D = Ahi*Bhi + Ahi*Blo + Alo*Bhi, fp32 accum (error ~2^-16).
__global__ __launch_bounds__(512) void gemm_mma_kernel(const float* __restrict__ x,
                                                       const float* __restrict__ a_src,
                                                       const float* __restrict__ a_dst,
                                                       const int* __restrict__ ei) {
    __shared__ uint16_t sA[2][128 * 72];   // 36 KB: [tier][row*72 + k]
    __shared__ float sAs[CC], sAd[CC];

    const int tid  = threadIdx.x;
    const int warp = tid >> 5;
    const int lane = tid & 31;
    const int mw   = warp >> 2;      // 0..3
    const int nw   = warp & 3;       // 0..3
    const int bm   = blockIdx.x * 128;
    const int g    = lane >> 2;      // row group within m8
    const int tq   = lane & 3;

    if (tid < CC) { sAs[tid] = a_src[tid]; sAd[tid] = a_dst[tid]; }

    float acc[2][8][4];
#pragma unroll
    for (int mt = 0; mt < 2; mt++)
#pragma unroll
        for (int j = 0; j < 8; j++)
#pragma unroll
            for (int q = 0; q < 4; q++) acc[mt][j][q] = 0.f;

    const uint32_t sA0 = smem_u32(&sA[0][0]);
    const uint32_t sA1 = smem_u32(&sA[1][0]);

    // register prefetch of A chunk
    float4 vreg[4];
#pragma unroll
    for (int i = 0; i < 4; i++) {
        int j  = tid + i * 512;
        int r  = j >> 4;
        int k4 = (j & 15) << 2;
        int gr = bm + r;
        vreg[i] = (gr < NN) ? *(const float4*)&x[gr * INF + k4]
                            : make_float4(0.f, 0.f, 0.f, 0.f);
    }

    for (int c = 0; c < 4; c++) {
        __syncthreads();   // protect smem reuse from previous chunk's ldmatrix
        // ---- convert prefetched A chunk into smem ----
#pragma unroll
        for (int i = 0; i < 4; i++) {
            int j  = tid + i * 512;
            int r  = j >> 4;
            int k4 = (j & 15) << 2;
            float4 v = vreg[i];
            __nv_bfloat16 h0 = __float2bfloat16(v.x), h1 = __float2bfloat16(v.y);
            __nv_bfloat16 h2 = __float2bfloat16(v.z), h3 = __float2bfloat16(v.w);
            __nv_bfloat16 l0 = __float2bfloat16(v.x - __bfloat162float(h0));
            __nv_bfloat16 l1 = __float2bfloat16(v.y - __bfloat162float(h1));
            __nv_bfloat16 l2 = __float2bfloat16(v.z - __bfloat162float(h2));
            __nv_bfloat16 l3 = __float2bfloat16(v.w - __bfloat162float(h3));
            int o = r * 72 + k4;
            *(uint2*)&sA[0][o] = make_uint2(pack_bf2(h0, h1), pack_bf2(h2, h3));
            *(uint2*)&sA[1][o] = make_uint2(pack_bf2(l0, l1), pack_bf2(l2, l3));
        }
        __syncthreads();

        // issue next chunk's loads (consumed next iteration, hidden under MMA)
        if (c < 3) {
#pragma unroll
            for (int i = 0; i < 4; i++) {
                int j  = tid + i * 512;
                int r  = j >> 4;
                int k4 = (j & 15) << 2;
                int gr = bm + r;
                vreg[i] = (gr < NN) ? *(const float4*)&x[gr * INF + (c + 1) * 64 + k4]
                                    : make_float4(0.f, 0.f, 0.f, 0.f);
            }
        }

        // ---- 4 k-steps of K=16 within this chunk ----
#pragma unroll
        for (int ks = 0; ks < 4; ks++) {
            const int gk = c * 4 + ks;
            uint32_t arow  = lane & 15;
            uint32_t ahalf = lane >> 4;
            uint32_t ahi0[4], ahi1[4], alo0[4], alo1[4];
            uint32_t off0 = ((mw * 32 + 0  + arow) * 72 + ks * 16 + ahalf * 8) * 2;
            uint32_t off1 = ((mw * 32 + 16 + arow) * 72 + ks * 16 + ahalf * 8) * 2;
            ldmat4(ahi0, sA0 + off0);
            ldmat4(ahi1, sA0 + off1);
            ldmat4(alo0, sA1 + off0);
            ldmat4(alo1, sA1 + off1);

            const uint2* bfh = &g_Bf[((0 * 16 + gk) * 32 + nw * 8) * 32 + lane];
            const uint2* bfl = &g_Bf[((1 * 16 + gk) * 32 + nw * 8) * 32 + lane];
#pragma unroll
            for (int j = 0; j < 8; j++) {
                uint2 bh = bfh[j * 32];
                uint2 bl = bfl[j * 32];
                mma16816(acc[0][j], ahi0, bh);
                mma16816(acc[1][j], ahi1, bh);
                mma16816(acc[0][j], ahi0, bl);
                mma16816(acc[1][j], ahi1, bl);
                mma16816(acc[0][j], alo0, bh);
                mma16816(acc[1][j], alo1, bh);
            }
        }
    }
    __syncthreads();

    // ---- epilogue: store h + fused logits ----
    float ps[2][2][2] = {}, pd[2][2][2] = {};   // [mt][rowhalf][head]
#pragma unroll
    for (int mt = 0; mt < 2; mt++) {
        int r0 = bm + mw * 32 + mt * 16 + g;
        int r1 = r0 + 8;
#pragma unroll
        for (int j = 0; j < 8; j++) {
            int col = nw * 64 + j * 8 + tq * 2;
            int hh  = j >> 2;
            float a0 = sAs[col], a1 = sAs[col + 1];
            float d0 = sAd[col], d1 = sAd[col + 1];
            ps[mt][0][hh] += acc[mt][j][0] * a0 + acc[mt][j][1] * a1;
            pd[mt][0][hh] += acc[mt][j][0] * d0 + acc[mt][j][1] * d1;
            ps[mt][1][hh] += acc[mt][j][2] * a0 + acc[mt][j][3] * a1;
            pd[mt][1][hh] += acc[mt][j][2] * d0 + acc[mt][j][3] * d1;
            if (r0 < NN)
                *(float2*)&g_h[r0 * CC + col] = make_float2(acc[mt][j][0], acc[mt][j][1]);
            if (r1 < NN)
                *(float2*)&g_h[r1 * CC + col] = make_float2(acc[mt][j][2], acc[mt][j][3]);
        }
    }
#pragma unroll
    for (int mt = 0; mt < 2; mt++)
#pragma unroll
        for (int hf = 0; hf < 2; hf++)
#pragma unroll
            for (int hh = 0; hh < 2; hh++) {
                ps[mt][hf][hh] += __shfl_xor_sync(0xffffffffu, ps[mt][hf][hh], 1, 4);
                ps[mt][hf][hh] += __shfl_xor_sync(0xffffffffu, ps[mt][hf][hh], 2, 4);
                pd[mt][hf][hh] += __shfl_xor_sync(0xffffffffu, pd[mt][hf][hh], 1, 4);
                pd[mt][hf][hh] += __shfl_xor_sync(0xffffffffu, pd[mt][hf][hh], 2, 4);
            }
    if (tq == 0) {
#pragma unroll
        for (int mt = 0; mt < 2; mt++) {
            int r0 = bm + mw * 32 + mt * 16 + g;
            int r1 = r0 + 8;
#pragma unroll
            for (int hh = 0; hh < 2; hh++) {
                int hcol = nw * 2 + hh;
                if (r0 < NN) {
                    g_ssrc[r0 * NH + hcol] = ps[mt][0][hh];
                    g_sdst[r0 * NH + hcol] = pd[mt][0][hh];
                }
                if (r1 < NN) {
                    g_ssrc[r1 * NH + hcol] = ps[mt][1][hh];
                    g_sdst[r1 * NH + hcol] = pd[mt][1][hh];
                }
            }
        }
    }

    // ---- histogram tail (independent of GEMM results; overlaps other waves) ----
    for (int e = blockIdx.x * 512 + tid; e < EE; e += gridDim.x * 512)
        atomicAdd(&g_deg[ei[EE + e]], 1);
}

// ---------------- 2) CSR build: 3-stage scan -> scatter ----------------
__global__ __launch_bounds__(256) void scan_bsum_kernel() {
    __shared__ int ws[8];
    int i = blockIdx.x * 256 + threadIdx.x;
    int v = (i < NN) ? g_deg[i] : 0;
    int lane = threadIdx.x & 31, wid = threadIdx.x >> 5;
#pragma unroll
    for (int off = 16; off; off >>= 1) v += __shfl_xor_sync(0xffffffffu, v, off);
    if (lane == 0) ws[wid] = v;
    __syncthreads();
    if (threadIdx.x == 0) {
        int s = 0;
#pragma unroll
        for (int w = 0; w < 8; w++) s += ws[w];
        g_bsum[blockIdx.x] = s;
    }
}

__global__ __launch_bounds__(256) void scan_boff_kernel() {
    __shared__ int ws[8];
    int t = threadIdx.x;
    int s = (t < NBLK) ? g_bsum[t] : 0;
    int lane = t & 31, wid = t >> 5;
    int v = s;
#pragma unroll
    for (int off = 1; off < 32; off <<= 1) {
        int u = __shfl_up_sync(0xffffffffu, v, off);
        if (lane >= off) v += u;
    }
    if (lane == 31) ws[wid] = v;
    __syncthreads();
    if (wid == 0 && lane < 8) {
        int w = ws[lane];
#pragma unroll
        for (int off = 1; off < 8; off <<= 1) {
            int u = __shfl_up_sync(0x000000ffu, w, off);
            if (lane >= off) w += u;
        }
        ws[lane] = w;
    }
    __syncthreads();
    int excl = v - s + (wid ? ws[wid - 1] : 0);
    if (t < NBLK) g_boff[t] = excl;
}

__global__ __launch_bounds__(256) void scan_write_kernel() {
    __shared__ int ws[8];
    int i = blockIdx.x * 256 + threadIdx.x;
    int s = (i < NN) ? g_deg[i] : 0;
    int lane = threadIdx.x & 31, wid = threadIdx.x >> 5;
    int v = s;
#pragma unroll
    for (int off = 1; off < 32; off <<= 1) {
        int u = __shfl_up_sync(0xffffffffu, v, off);
        if (lane >= off) v += u;
    }
    if (lane == 31) ws[wid] = v;
    __syncthreads();
    if (wid == 0 && lane < 8) {
        int w = ws[lane];
#pragma unroll
        for (int off = 1; off < 8; off <<= 1) {
            int u = __shfl_up_sync(0x000000ffu, w, off);
            if (lane >= off) w += u;
        }
        ws[lane] = w;
    }
    __syncthreads();
    int excl = v - s + (wid ? ws[wid - 1] : 0) + g_boff[blockIdx.x];
    if (i < NN) {
        g_rowptr[i] = excl;
        g_cursor[i] = excl;
    }
}

__global__ void scatter_kernel(const int* __restrict__ ei) {
    int e = blockIdx.x * blockDim.x + threadIdx.x;
    if (e >= EE) return;
    int src = ei[e];
    int dst = ei[EE + e];
    int p = atomicAdd(&g_cursor[dst], 1);
    g_csrc[p] = src;
}

// ---------------- 3) single-pass aggregation ----------------
// out[dst] = (sum_e exp_e * h[src_e]) / (sum_e exp_e + EPS)  — algebraically
// identical to per-edge normalization. One warp per dst; lane l owns output
// floats [8l, 8l+8) (head l/4). (csrc, ssrc) software-pipelined 1 deep so the
// 1KB h-row gather issues at loop top. No output atomics, no denominator pass.
__global__ __launch_bounds__(256) void aggregate_csr_kernel(float* __restrict__ out) {
    int warp = (blockIdx.x * blockDim.x + threadIdx.x) >> 5;
    int lane = threadIdx.x & 31;
    if (warp >= NN) return;
    const int dst   = warp;
    const int start = g_rowptr[dst];
    const int end   = g_rowptr[dst + 1];

    // lanes 0..7 hold this dst's logit for head 'lane'
    float sdl = (lane < NH) ? g_sdst[dst * NH + lane] : 0.f;

    float4 acc0 = make_float4(0.f, 0.f, 0.f, 0.f);
    float4 acc1 = make_float4(0.f, 0.f, 0.f, 0.f);
    float  tot  = 0.f;

    const float4* h4 = (const float4*)g_h;
    int i = start;
    int src = (i < end) ? g_csrc[i] : 0;
    float aval = (lane < NH) ? g_ssrc[src * NH + lane] : 0.f;

    for (; i < end; i++) {
        // prefetch next edge's id + src logit (row 0 is always valid)
        int nsrc = (i + 1 < end) ? g_csrc[i + 1] : 0;
        float naval = (lane < NH) ? g_ssrc[nsrc * NH + lane] : 0.f;

        float w = 0.f;
        if (lane < NH) {
            float v = aval + sdl;
            v = v > 0.f ? v : 0.2f * v;
            w = __expf(v);
            tot += w;
        }
        float wv = __shfl_sync(0xffffffffu, w, lane >> 2);
        float4 v0 = h4[src * (CC / 4) + lane * 2];
        float4 v1 = h4[src * (CC / 4) + lane * 2 + 1];
        acc0.x += wv * v0.x; acc0.y += wv * v0.y;
        acc0.z += wv * v0.z; acc0.w += wv * v0.w;
        acc1.x += wv * v1.x; acc1.y += wv * v1.y;
        acc1.z += wv * v1.z; acc1.w += wv * v1.w;

        src = nsrc;
        aval = naval;
    }

    // normalize: tot lives on lane h (h<8); broadcast to its 4 owner lanes
    float t   = __shfl_sync(0xffffffffu, tot, lane >> 2);
    float inv = 1.0f / (t + 1e-8f);
    acc0.x *= inv; acc0.y *= inv; acc0.z *= inv; acc0.w *= inv;
    acc1.x *= inv; acc1.y *= inv; acc1.z *= inv; acc1.w *= inv;

    float4* o4 = (float4*)(out + dst * CC);
    o4[lane * 2]     = acc0;
    o4[lane * 2 + 1] = acc1;
}

// ---------------- launch ----------------
extern "C" void kernel_launch(void* const* d_in, const int* in_sizes, int n_in,
                              void* d_out, int out_size) {
    const float* x     = (const float*)d_in[0];
    const int*   ei    = (const int*)d_in[1];
    const float* W     = (const float*)d_in[2];
    const float* a_src = (const float*)d_in[3];
    const float* a_dst = (const float*)d_in[4];
    float* out = (float*)d_out;

    init_kernel<<<NBLK + 128, 256>>>(W);

    gemm_mma_kernel<<<(NN + 127) / 128, 512>>>(x, a_src, a_dst, ei);

    scan_bsum_kernel<<<NBLK, 256>>>();
    scan_boff_kernel<<<1, 256>>>();
    scan_write_kernel<<<NBLK, 256>>>();
    scatter_kernel<<<(EE + 255) / 256, 256>>>(ei);

    aggregate_csr_kernel<<<NN / 8, 256>>>(out);
}